// round 14
// baseline (speedup 1.0000x reference)
#include <cuda_runtime.h>
#include <math.h>

#define Bb   16
#define Nn   512
#define Ff   512
#define Hh   16
#define DH   32
#define HIDD 2048
#define LLa  6
#define MM   (Bb*Nn)      // 8192 rows

// ---------------- scratch (device globals; zero-initialized) ----------------
__device__ float g_x [Bb*Nn*Ff];
__device__ float g_q [Bb*Nn*Ff];
__device__ float g_k [Bb*Nn*Ff];
__device__ float g_v [Bb*Nn*Ff];
__device__ float g_ao[Bb*Nn*Ff];
__device__ float g_h [Bb*Nn*HIDD];

__device__ __forceinline__ float warp_sum(float v) {
    #pragma unroll
    for (int o = 16; o; o >>= 1) v += __shfl_xor_sync(0xffffffffu, v, o);
    return v;
}

__device__ __forceinline__ void mma_tf32(float* d, const float* a, const float* b) {
    asm volatile(
        "mma.sync.aligned.m16n8k8.row.col.f32.tf32.tf32.f32 "
        "{%0,%1,%2,%3}, {%4,%5,%6,%7}, {%8,%9}, {%0,%1,%2,%3};"
        : "+f"(d[0]), "+f"(d[1]), "+f"(d[2]), "+f"(d[3])
        : "r"(__float_as_uint(a[0])), "r"(__float_as_uint(a[1])),
          "r"(__float_as_uint(a[2])), "r"(__float_as_uint(a[3])),
          "r"(__float_as_uint(b[0])), "r"(__float_as_uint(b[1])));
}

__device__ __forceinline__ void cp_async16(float* smem, const float* gmem) {
    unsigned sa = (unsigned)__cvta_generic_to_shared(smem);
    asm volatile("cp.async.cg.shared.global [%0], [%1], 16;\n" :: "r"(sa), "l"(gmem));
}
__device__ __forceinline__ void cp_commit() {
    asm volatile("cp.async.commit_group;\n");
}
template<int N>
__device__ __forceinline__ void cp_wait() {
    asm volatile("cp.async.wait_group %0;\n" :: "n"(N));
}

// ---------------- input embedding ----------------
__global__ void build_x_kernel(const float* __restrict__ nfeats,
                               const int*   __restrict__ degrees,
                               const int*   __restrict__ num_nodes,
                               const float* __restrict__ deg_in,
                               const float* __restrict__ deg_out,
                               float* __restrict__ x)
{
    int idx = blockIdx.x * blockDim.x + threadIdx.x;
    int f  = idx & (Ff - 1);
    int bn = idx >> 9;
    int n  = bn & (Nn - 1);
    int b  = bn >> 9;
    float val = 0.f;
    if (n < num_nodes[b]) {
        int d = degrees[bn];
        d = min(max(d, 0), 100);
        val = nfeats[idx] + deg_in[d * Ff + f] + deg_out[d * Ff + f];
    }
    x[idx] = val;
}

// ---------------- persistent tf32 GEMM 64x64x16, 128 threads, 4 stages -------
#define BM 64
#define BN 64
#define BK 16
#define STG 4
#define GTHR 128
#define SA 20
#define SB 72
#define ASZ (BM * SA)
#define BSZ (BK * SB)
#define STG_FLOATS (ASZ + BSZ)
#define GEMM_SMEM (STG * STG_FLOATS * 4)   // 38912 bytes
#define PERSIST_BLKS 592                   // 148 SMs x 4

template<int EPI>
__device__ __forceinline__ void gemm_body(
    const float* __restrict__ A, const float* __restrict__ W,
    const float* __restrict__ bias, const float* __restrict__ resid,
    float* __restrict__ C, int K, int Nc, float alpha, int bm, int bn)
{
    extern __shared__ __align__(16) float sm[];

    const int tid  = threadIdx.x;
    const int wid  = tid >> 5, lane = tid & 31;
    const int g    = lane >> 2, tig = lane & 3;
    const int wm   = (wid & 1) * 32;
    const int wn   = (wid >> 1) * 32;
    const int KT   = K >> 4;

    const float* Ab = A + (size_t)bm * K;
    const float* Wb = W + bn;

    float acc[2][4][4];
    #pragma unroll
    for (int i = 0; i < 2; i++)
        #pragma unroll
        for (int j = 0; j < 4; j++)
            #pragma unroll
            for (int q = 0; q < 4; q++) acc[i][j][q] = 0.f;

    auto issue = [&](int stg, int kt) {
        float* As = sm + stg * STG_FLOATS;
        float* Bs = As + ASZ;
        const int k0 = kt * BK;
        #pragma unroll
        for (int i = 0; i < 2; i++) {
            int idx = tid + GTHR * i;
            int m = idx >> 2, kq = (idx & 3) * 4;
            cp_async16(As + m * SA + kq, Ab + (size_t)m * K + k0 + kq);
        }
        #pragma unroll
        for (int i = 0; i < 2; i++) {
            int idx = tid + GTHR * i;
            int kr = idx >> 4, c4 = (idx & 15) * 4;
            cp_async16(Bs + kr * SB + c4, Wb + (size_t)(k0 + kr) * Nc + c4);
        }
    };

    #pragma unroll
    for (int s = 0; s < STG - 1; s++) { issue(s, s); cp_commit(); }

    int stg = 0, stg_next = STG - 1;
    for (int kt = 0; kt < KT; kt++) {
        cp_wait<STG - 2>();
        __syncthreads();

        int knext = kt + STG - 1;
        if (knext < KT) issue(stg_next, knext);
        cp_commit();
        if (++stg_next == STG) stg_next = 0;

        const float* As = sm + stg * STG_FLOATS;
        const float* Bs = As + ASZ;
        if (++stg == STG) stg = 0;

        #pragma unroll
        for (int s = 0; s < 2; s++) {
            const int k8 = s * 8;
            float af[2][4];
            #pragma unroll
            for (int im = 0; im < 2; im++) {
                int mb = wm + im * 16;
                af[im][0] = As[(mb + g    ) * SA + k8 + tig    ];
                af[im][1] = As[(mb + g + 8) * SA + k8 + tig    ];
                af[im][2] = As[(mb + g    ) * SA + k8 + tig + 4];
                af[im][3] = As[(mb + g + 8) * SA + k8 + tig + 4];
            }
            #pragma unroll
            for (int in_ = 0; in_ < 4; in_++) {
                int nb = wn + in_ * 8;
                float bf[2];
                bf[0] = Bs[(k8 + tig    ) * SB + nb + g];
                bf[1] = Bs[(k8 + tig + 4) * SB + nb + g];
                #pragma unroll
                for (int im = 0; im < 2; im++)
                    mma_tf32(acc[im][in_], af[im], bf);
            }
        }
    }

    #pragma unroll
    for (int in_ = 0; in_ < 4; in_++) {
        int n = bn + wn + in_ * 8 + 2 * tig;
        float2 bv = *(const float2*)&bias[n];
        #pragma unroll
        for (int im = 0; im < 2; im++) {
            #pragma unroll
            for (int half = 0; half < 2; half++) {
                int m = bm + wm + im * 16 + g + half * 8;
                float2 r;
                r.x = acc[im][in_][half * 2 + 0] + bv.x;
                r.y = acc[im][in_][half * 2 + 1] + bv.y;
                if (EPI == 0) { r.x *= alpha; r.y *= alpha; }
                else if (EPI == 1) { r.x = fmaxf(r.x, 0.f); r.y = fmaxf(r.y, 0.f); }
                else {
                    float2 rr = *(const float2*)&resid[(size_t)m * Nc + n];
                    r.x += rr.x; r.y += rr.y;
                }
                *(float2*)&C[(size_t)m * Nc + n] = r;
            }
        }
    }
}

// persistent wrapper: grid-stride over tiles; whole block skips invalid tiles
template<int EPI>
__global__ void __launch_bounds__(GTHR, 5)
gemm_persist(const float* __restrict__ A, const float* __restrict__ W,
             const float* __restrict__ bias, const float* __restrict__ resid,
             float* __restrict__ C, int K, int Nc, float alpha,
             const int* __restrict__ num_nodes, int tilesX)
{
    const int tilesTot = tilesX * (MM / BM);
    for (int t = blockIdx.x; t < tilesTot; t += gridDim.x) {
        const int bm = (t / tilesX) * BM;
        const int bn = (t % tilesX) * BN;
        if ((bm & (Nn - 1)) >= __ldg(&num_nodes[bm >> 9])) continue;
        gemm_body<EPI>(A, W, bias, resid, C, K, Nc, alpha, bm, bn);
    }
}

// persistent fused QKV: tiles = 3 * tilesX * tilesY, z selects projection
__global__ void __launch_bounds__(GTHR, 5)
qkv_persist(const float* __restrict__ A,
            const float* __restrict__ Wq, const float* __restrict__ Wk,
            const float* __restrict__ Wv,
            const float* __restrict__ bq, const float* __restrict__ bk,
            const float* __restrict__ bv,
            float* __restrict__ Cq, float* __restrict__ Ck, float* __restrict__ Cv,
            float qscale, const int* __restrict__ num_nodes)
{
    const int tilesX = Ff / BN;                 // 8
    const int tilesPer = tilesX * (MM / BM);    // 1024
    const int tilesTot = 3 * tilesPer;
    for (int t = blockIdx.x; t < tilesTot; t += gridDim.x) {
        const int z  = t / tilesPer;
        const int tt = t % tilesPer;
        const int bm = (tt / tilesX) * BM;
        const int bn = (tt % tilesX) * BN;
        if ((bm & (Nn - 1)) >= __ldg(&num_nodes[bm >> 9])) continue;
        const float* W = (z == 0) ? Wq : (z == 1) ? Wk : Wv;
        const float* b = (z == 0) ? bq : (z == 1) ? bk : bv;
        float*       C = (z == 0) ? Cq : (z == 1) ? Ck : Cv;
        float alpha = (z == 0) ? qscale : 1.f;
        gemm_body<0>(A, W, b, nullptr, C, Ff, Ff, alpha, bm, bn);
    }
}

// ---------------- flash attention (R12 version: dist_idx + sSpH) -------------
#define FS_K 36
#define FS_V 40
#define FS_P 68
#define KSZ (64 * FS_K)
#define VSZ (64 * FS_V)
#define FO_K 0
#define FO_V (FO_K + 2 * KSZ)
#define FO_P (FO_V + 2 * VSZ)
#define FO_SPH (FO_P + 128 * FS_P)
#define ATTN_SMEM_BYTES ((FO_SPH + 16) * 4)

__global__ void __launch_bounds__(256, 2)
attn_flash(const float* __restrict__ q, const float* __restrict__ k,
           const float* __restrict__ v,
           const int*   __restrict__ dist_idx,
           const float* __restrict__ spatial,
           const int*   __restrict__ num_nodes,
           float* __restrict__ o)
{
    extern __shared__ __align__(16) float sm[];
    float* sKb  = sm + FO_K;
    float* sVb  = sm + FO_V;
    float* sP   = sm + FO_P;
    float* sSpH = sm + FO_SPH;

    const int tid = threadIdx.x;
    const int it = blockIdx.x, h = blockIdx.y, b = blockIdx.z;
    const int i0 = it * 128;
    const int nn = num_nodes[b];
    if (i0 >= nn) return;

    const int jt_max = (nn + 63) >> 6;

    const int w = tid >> 5, lane = tid & 31;
    const int g = lane >> 2, tig = lane & 3;
    const int wm = w * 16;

    if (tid < 12) sSpH[tid] = spatial[tid * Hh + h];

    const float* kb0 = k + ((size_t)b * Nn) * Ff + h * DH;
    const float* vb0 = v + ((size_t)b * Nn) * Ff + h * DH;

    auto issue_kv = [&](int buf, int j0) {
        float* sK = sKb + buf * KSZ;
        float* sV = sVb + buf * VSZ;
        #pragma unroll
        for (int i = 0; i < 2; i++) {
            int idx = tid + 256 * i;
            int r = idx >> 3, d4 = (idx & 7) * 4;
            cp_async16(sK + r * FS_K + d4, kb0 + (size_t)(j0 + r) * Ff + d4);
            cp_async16(sV + r * FS_V + d4, vb0 + (size_t)(j0 + r) * Ff + d4);
        }
    };

    issue_kv(0, 0); cp_commit();

    const int rg  = wm + g;
    const int rg8 = wm + g + 8;

    const float* qb = q + ((size_t)(b * Nn + i0)) * Ff + h * DH;
    float qreg[4][4];
    #pragma unroll
    for (int kt = 0; kt < 4; kt++) {
        const int k8 = kt * 8;
        qreg[kt][0] = qb[(size_t)rg  * Ff + k8 + tig    ];
        qreg[kt][1] = qb[(size_t)rg8 * Ff + k8 + tig    ];
        qreg[kt][2] = qb[(size_t)rg  * Ff + k8 + tig + 4];
        qreg[kt][3] = qb[(size_t)rg8 * Ff + k8 + tig + 4];
    }

    const bool vi0 = (i0 + rg ) < nn;
    const bool vi1 = (i0 + rg8) < nn;
    const int* dr0 = dist_idx + ((size_t)(b * Nn + i0 + rg )) * Nn;
    const int* dr1 = dist_idx + ((size_t)(b * Nn + i0 + rg8)) * Nn;

    float m_run0 = -3.4e38f, m_run1 = -3.4e38f;
    float l_run0 = 0.f, l_run1 = 0.f;

    float oacc[4][4];
    #pragma unroll
    for (int i = 0; i < 4; i++)
        #pragma unroll
        for (int j = 0; j < 4; j++) oacc[i][j] = 0.f;

    for (int jt = 0; jt < jt_max; jt++) {
        const int j0 = jt * 64;
        const int buf = jt & 1;
        const float* sK = sKb + buf * KSZ;
        const float* sV = sVb + buf * VSZ;

        cp_wait<0>();
        __syncthreads();

        if (jt + 1 < jt_max) { issue_kv(buf ^ 1, j0 + 64); }
        cp_commit();

        float acc[8][4];
        #pragma unroll
        for (int i = 0; i < 8; i++)
            #pragma unroll
            for (int j = 0; j < 4; j++) acc[i][j] = 0.f;

        #pragma unroll
        for (int kt = 0; kt < 4; kt++) {
            const int k8 = kt * 8;
            #pragma unroll
            for (int nt = 0; nt < 8; nt++) {
                int nb = nt * 8;
                float bf[2];
                bf[0] = sK[(nb + g) * FS_K + k8 + tig    ];
                bf[1] = sK[(nb + g) * FS_K + k8 + tig + 4];
                mma_tf32(acc[nt], qreg[kt], bf);
            }
        }

        #pragma unroll
        for (int nt = 0; nt < 8; nt++) {
            int colb = j0 + nt * 8 + 2 * tig;
            int2 d0 = *(const int2*)(dr0 + colb);
            int2 d1 = *(const int2*)(dr1 + colb);
            bool m00 = (colb     >= nn) || ((!vi0) && (colb     >= 1));
            bool m01 = (colb + 1 >= nn) || ((!vi0) && (colb + 1 >= 1));
            bool m10 = (colb     >= nn) || ((!vi1) && (colb     >= 1));
            bool m11 = (colb + 1 >= nn) || ((!vi1) && (colb + 1 >= 1));
            acc[nt][0] = m00 ? -1e9f : acc[nt][0] + sSpH[d0.x];
            acc[nt][1] = m01 ? -1e9f : acc[nt][1] + sSpH[d0.y];
            acc[nt][2] = m10 ? -1e9f : acc[nt][2] + sSpH[d1.x];
            acc[nt][3] = m11 ? -1e9f : acc[nt][3] + sSpH[d1.y];
        }

        float tm0 = -3.4e38f, tm1 = -3.4e38f;
        #pragma unroll
        for (int nt = 0; nt < 8; nt++) {
            tm0 = fmaxf(tm0, fmaxf(acc[nt][0], acc[nt][1]));
            tm1 = fmaxf(tm1, fmaxf(acc[nt][2], acc[nt][3]));
        }
        #pragma unroll
        for (int off = 1; off <= 2; off <<= 1) {
            tm0 = fmaxf(tm0, __shfl_xor_sync(0xffffffffu, tm0, off));
            tm1 = fmaxf(tm1, __shfl_xor_sync(0xffffffffu, tm1, off));
        }

        const float nm0 = fmaxf(m_run0, tm0);
        const float nm1 = fmaxf(m_run1, tm1);
        const float f0 = __expf(m_run0 - nm0);
        const float f1 = __expf(m_run1 - nm1);
        m_run0 = nm0; m_run1 = nm1;

        float s0 = 0.f, s1 = 0.f;
        #pragma unroll
        for (int nt = 0; nt < 8; nt++) {
            int lcol = nt * 8 + 2 * tig;
            float p00 = __expf(acc[nt][0] - nm0);
            float p01 = __expf(acc[nt][1] - nm0);
            float p10 = __expf(acc[nt][2] - nm1);
            float p11 = __expf(acc[nt][3] - nm1);
            s0 += p00 + p01;
            s1 += p10 + p11;
            *(float2*)&sP[rg  * FS_P + lcol] = make_float2(p00, p01);
            *(float2*)&sP[rg8 * FS_P + lcol] = make_float2(p10, p11);
        }
        #pragma unroll
        for (int off = 1; off <= 2; off <<= 1) {
            s0 += __shfl_xor_sync(0xffffffffu, s0, off);
            s1 += __shfl_xor_sync(0xffffffffu, s1, off);
        }
        l_run0 = l_run0 * f0 + s0;
        l_run1 = l_run1 * f1 + s1;

        __syncwarp();

        #pragma unroll
        for (int nt = 0; nt < 4; nt++) {
            oacc[nt][0] *= f0; oacc[nt][1] *= f0;
            oacc[nt][2] *= f1; oacc[nt][3] *= f1;
        }

        #pragma unroll
        for (int kt = 0; kt < 8; kt++) {
            const int kc = kt * 8;
            float a[4];
            a[0] = sP[rg  * FS_P + kc + tig    ];
            a[1] = sP[rg8 * FS_P + kc + tig    ];
            a[2] = sP[rg  * FS_P + kc + tig + 4];
            a[3] = sP[rg8 * FS_P + kc + tig + 4];
            #pragma unroll
            for (int nt = 0; nt < 4; nt++) {
                int nb = nt * 8;
                float bf[2];
                bf[0] = sV[(kc + tig    ) * FS_V + nb + g];
                bf[1] = sV[(kc + tig + 4) * FS_V + nb + g];
                mma_tf32(oacc[nt], a, bf);
            }
        }
    }

    const float inv0 = 1.f / l_run0;
    const float inv1 = 1.f / l_run1;
    #pragma unroll
    for (int nt = 0; nt < 4; nt++) {
        int col = h * DH + nt * 8 + 2 * tig;
        *(float2*)&o[((size_t)(b * Nn + i0 + rg )) * Ff + col] =
            make_float2(oacc[nt][0] * inv0, oacc[nt][1] * inv0);
        *(float2*)&o[((size_t)(b * Nn + i0 + rg8)) * Ff + col] =
            make_float2(oacc[nt][2] * inv1, oacc[nt][3] * inv1);
    }
}

// ---------------- LayerNorm: one warp per row, shuffle-only ----------------
__global__ void __launch_bounds__(256)
ln_kernel(float* __restrict__ x,
          const float* __restrict__ gamma,
          const float* __restrict__ beta,
          const int* __restrict__ num_nodes)
{
    const int warp = threadIdx.x >> 5, lane = threadIdx.x & 31;
    const int row = blockIdx.x * 8 + warp;
    if ((row & (Nn - 1)) >= __ldg(&num_nodes[row >> 9])) return;

    float* xr = x + (size_t)row * Ff;
    float4 v[4];
    #pragma unroll
    for (int i = 0; i < 4; i++)
        v[i] = *(const float4*)(xr + lane * 4 + i * 128);

    float s = 0.f;
    #pragma unroll
    for (int i = 0; i < 4; i++) s += v[i].x + v[i].y + v[i].z + v[i].w;
    s = warp_sum(s);
    const float mean = s * (1.f / 512.f);

    float s2 = 0.f;
    #pragma unroll
    for (int i = 0; i < 4; i++) {
        float dx = v[i].x - mean, dy = v[i].y - mean;
        float dz = v[i].z - mean, dw = v[i].w - mean;
        s2 += dx * dx + dy * dy + dz * dz + dw * dw;
    }
    s2 = warp_sum(s2);
    const float inv = rsqrtf(s2 * (1.f / 512.f) + 1e-5f);

    #pragma unroll
    for (int i = 0; i < 4; i++) {
        float4 gm = *(const float4*)(gamma + lane * 4 + i * 128);
        float4 bt = *(const float4*)(beta  + lane * 4 + i * 128);
        float4 r;
        r.x = (v[i].x - mean) * inv * gm.x + bt.x;
        r.y = (v[i].y - mean) * inv * gm.y + bt.y;
        r.z = (v[i].z - mean) * inv * gm.z + bt.z;
        r.w = (v[i].w - mean) * inv * gm.w + bt.w;
        *(float4*)(xr + lane * 4 + i * 128) = r;
    }
}

// ---------------- pooled classifier ----------------
__global__ void pool_kernel(const float* __restrict__ x,
                            const int*   __restrict__ num_nodes,
                            const float* __restrict__ clf_w,
                            const float* __restrict__ clf_b,
                            float* __restrict__ out)
{
    __shared__ float red[8];
    const int b = blockIdx.x, tid = threadIdx.x;
    const int lane = tid & 31, warp = tid >> 5;
    const int nn = num_nodes[b];
    const float* xb = x + (size_t)b * Nn * Ff;
    float local = 0.f;
    const int total = nn * Ff;
    for (int i = tid; i < total; i += 256)
        local += xb[i] * clf_w[i & (Ff - 1)];
    local = warp_sum(local);
    if (lane == 0) red[warp] = local;
    __syncthreads();
    if (tid == 0) {
        float tot = 0.f;
        #pragma unroll
        for (int i = 0; i < 8; i++) tot += red[i];
        float z = tot / (float)nn + clf_b[0];
        out[b] = 1.f / (1.f + expf(-z));
    }
}

// ---------------- host launcher ----------------
extern "C" void kernel_launch(void* const* d_in, const int* in_sizes, int n_in,
                              void* d_out, int out_size)
{
    const float* nfeats   = (const float*)d_in[0];
    const int*   degrees  = (const int*)  d_in[1];
    const int*   dist_idx = (const int*)  d_in[2];
    const int*   num_nodes= (const int*)  d_in[3];
    const float* deg_in   = (const float*)d_in[4];
    const float* deg_out  = (const float*)d_in[5];
    const float* spatial  = (const float*)d_in[6];
    const float* Wq = (const float*)d_in[7];
    const float* bq = (const float*)d_in[8];
    const float* Wk = (const float*)d_in[9];
    const float* bk = (const float*)d_in[10];
    const float* Wv = (const float*)d_in[11];
    const float* bv = (const float*)d_in[12];
    const float* Wo = (const float*)d_in[13];
    const float* bo = (const float*)d_in[14];
    const float* ln1_s = (const float*)d_in[15];
    const float* ln1_b = (const float*)d_in[16];
    const float* W1 = (const float*)d_in[17];
    const float* b1 = (const float*)d_in[18];
    const float* W2 = (const float*)d_in[19];
    const float* b2 = (const float*)d_in[20];
    const float* ln2_s = (const float*)d_in[21];
    const float* ln2_b = (const float*)d_in[22];
    const float* clf_w = (const float*)d_in[23];
    const float* clf_b = (const float*)d_in[24];
    float* out = (float*)d_out;

    float *px, *pq, *pk, *pv, *pao, *ph;
    cudaGetSymbolAddress((void**)&px,  g_x);
    cudaGetSymbolAddress((void**)&pq,  g_q);
    cudaGetSymbolAddress((void**)&pk,  g_k);
    cudaGetSymbolAddress((void**)&pv,  g_v);
    cudaGetSymbolAddress((void**)&pao, g_ao);
    cudaGetSymbolAddress((void**)&ph,  g_h);

    cudaFuncSetAttribute(attn_flash,
                         cudaFuncAttributeMaxDynamicSharedMemorySize,
                         ATTN_SMEM_BYTES);
    cudaFuncSetAttribute(qkv_persist,
                         cudaFuncAttributeMaxDynamicSharedMemorySize, GEMM_SMEM);
    cudaFuncSetAttribute(gemm_persist<0>,
                         cudaFuncAttributeMaxDynamicSharedMemorySize, GEMM_SMEM);
    cudaFuncSetAttribute(gemm_persist<1>,
                         cudaFuncAttributeMaxDynamicSharedMemorySize, GEMM_SMEM);
    cudaFuncSetAttribute(gemm_persist<2>,
                         cudaFuncAttributeMaxDynamicSharedMemorySize, GEMM_SMEM);

    build_x_kernel<<<(Bb * Nn * Ff) / 256, 256>>>(nfeats, degrees, num_nodes,
                                                  deg_in, deg_out, px);

    const float scale = 0.17677669529663687f;  // 1/sqrt(32)

    for (int l = 0; l < LLa; l++) {
        qkv_persist<<<PERSIST_BLKS, GTHR, GEMM_SMEM>>>(
            px,
            Wq + (size_t)l * Ff * Ff, Wk + (size_t)l * Ff * Ff, Wv + (size_t)l * Ff * Ff,
            bq + l * Ff, bk + l * Ff, bv + l * Ff,
            pq, pk, pv, scale, num_nodes);

        attn_flash<<<dim3(Nn / 128, Hh, Bb), 256, ATTN_SMEM_BYTES>>>(
            pq, pk, pv, dist_idx, spatial, num_nodes, pao);

        gemm_persist<2><<<PERSIST_BLKS, GTHR, GEMM_SMEM>>>(
            pao, Wo + (size_t)l * Ff * Ff, bo + l * Ff, px, px,
            Ff, Ff, 1.f, num_nodes, Ff / BN);
        ln_kernel<<<MM / 8, 256>>>(px, ln1_s + l * Ff, ln1_b + l * Ff, num_nodes);

        gemm_persist<1><<<PERSIST_BLKS, GTHR, GEMM_SMEM>>>(
            px, W1 + (size_t)l * Ff * HIDD, b1 + l * HIDD, nullptr, ph,
            Ff, HIDD, 1.f, num_nodes, HIDD / BN);
        gemm_persist<2><<<PERSIST_BLKS, GTHR, GEMM_SMEM>>>(
            ph, W2 + (size_t)l * HIDD * Ff, b2 + l * Ff, px, px,
            HIDD, Ff, 1.f, num_nodes, Ff / BN);
        ln_kernel<<<MM / 8, 256>>>(px, ln2_s + l * Ff, ln2_b + l * Ff, num_nodes);
    }

    pool_kernel<<<Bb, 256>>>(px, num_nodes, clf_w, clf_b, out);
}

// round 15
// speedup vs baseline: 1.1562x; 1.1562x over previous
#include <cuda_runtime.h>
#include <math.h>

#define Bb   16
#define Nn   512
#define Ff   512
#define Hh   16
#define DH   32
#define HIDD 2048
#define LLa  6
#define MM   (Bb*Nn)      // 8192 rows

// ---------------- scratch (device globals; zero-initialized) ----------------
__device__ float g_x [Bb*Nn*Ff];
__device__ float g_q [Bb*Nn*Ff];
__device__ float g_k [Bb*Nn*Ff];
__device__ float g_v [Bb*Nn*Ff];
__device__ float g_ao[Bb*Nn*Ff];
__device__ float g_h [Bb*Nn*HIDD];

__device__ __forceinline__ float warp_sum(float v) {
    #pragma unroll
    for (int o = 16; o; o >>= 1) v += __shfl_xor_sync(0xffffffffu, v, o);
    return v;
}

__device__ __forceinline__ void mma_tf32(float* d, const float* a, const float* b) {
    asm volatile(
        "mma.sync.aligned.m16n8k8.row.col.f32.tf32.tf32.f32 "
        "{%0,%1,%2,%3}, {%4,%5,%6,%7}, {%8,%9}, {%0,%1,%2,%3};"
        : "+f"(d[0]), "+f"(d[1]), "+f"(d[2]), "+f"(d[3])
        : "r"(__float_as_uint(a[0])), "r"(__float_as_uint(a[1])),
          "r"(__float_as_uint(a[2])), "r"(__float_as_uint(a[3])),
          "r"(__float_as_uint(b[0])), "r"(__float_as_uint(b[1])));
}

__device__ __forceinline__ void cp_async16(float* smem, const float* gmem) {
    unsigned sa = (unsigned)__cvta_generic_to_shared(smem);
    asm volatile("cp.async.cg.shared.global [%0], [%1], 16;\n" :: "r"(sa), "l"(gmem));
}
__device__ __forceinline__ void cp_commit() {
    asm volatile("cp.async.commit_group;\n");
}
template<int N>
__device__ __forceinline__ void cp_wait() {
    asm volatile("cp.async.wait_group %0;\n" :: "n"(N));
}

// ---------------- input embedding ----------------
__global__ void build_x_kernel(const float* __restrict__ nfeats,
                               const int*   __restrict__ degrees,
                               const int*   __restrict__ num_nodes,
                               const float* __restrict__ deg_in,
                               const float* __restrict__ deg_out,
                               float* __restrict__ x)
{
    int idx = blockIdx.x * blockDim.x + threadIdx.x;
    int f  = idx & (Ff - 1);
    int bn = idx >> 9;
    int n  = bn & (Nn - 1);
    int b  = bn >> 9;
    float val = 0.f;
    if (n < num_nodes[b]) {
        int d = degrees[bn];
        d = min(max(d, 0), 100);
        val = nfeats[idx] + deg_in[d * Ff + f] + deg_out[d * Ff + f];
    }
    x[idx] = val;
}

// ============ GEMM variant A: 64x64x16, 128 threads, 4 stages (R12) =========
#define BM 64
#define BN 64
#define BK 16
#define STG 4
#define GTHR 128
#define SA 20
#define SB 72
#define ASZ (BM * SA)
#define BSZ (BK * SB)
#define STG_FLOATS (ASZ + BSZ)
#define GEMM_SMEM (STG * STG_FLOATS * 4)   // 38912 bytes

template<int EPI>
__device__ __forceinline__ void gemm_body(
    const float* __restrict__ A, const float* __restrict__ W,
    const float* __restrict__ bias, const float* __restrict__ resid,
    float* __restrict__ C, int K, int Nc, float alpha, int bm, int bn)
{
    extern __shared__ __align__(16) float sm[];

    const int tid  = threadIdx.x;
    const int wid  = tid >> 5, lane = tid & 31;
    const int g    = lane >> 2, tig = lane & 3;
    const int wm   = (wid & 1) * 32;
    const int wn   = (wid >> 1) * 32;
    const int KT   = K >> 4;

    const float* Ab = A + (size_t)bm * K;
    const float* Wb = W + bn;

    float acc[2][4][4];
    #pragma unroll
    for (int i = 0; i < 2; i++)
        #pragma unroll
        for (int j = 0; j < 4; j++)
            #pragma unroll
            for (int q = 0; q < 4; q++) acc[i][j][q] = 0.f;

    auto issue = [&](int stg, int kt) {
        float* As = sm + stg * STG_FLOATS;
        float* Bs = As + ASZ;
        const int k0 = kt * BK;
        #pragma unroll
        for (int i = 0; i < 2; i++) {
            int idx = tid + GTHR * i;
            int m = idx >> 2, kq = (idx & 3) * 4;
            cp_async16(As + m * SA + kq, Ab + (size_t)m * K + k0 + kq);
        }
        #pragma unroll
        for (int i = 0; i < 2; i++) {
            int idx = tid + GTHR * i;
            int kr = idx >> 4, c4 = (idx & 15) * 4;
            cp_async16(Bs + kr * SB + c4, Wb + (size_t)(k0 + kr) * Nc + c4);
        }
    };

    #pragma unroll
    for (int s = 0; s < STG - 1; s++) { issue(s, s); cp_commit(); }

    int stg = 0, stg_next = STG - 1;
    for (int kt = 0; kt < KT; kt++) {
        cp_wait<STG - 2>();
        __syncthreads();

        int knext = kt + STG - 1;
        if (knext < KT) issue(stg_next, knext);
        cp_commit();
        if (++stg_next == STG) stg_next = 0;

        const float* As = sm + stg * STG_FLOATS;
        const float* Bs = As + ASZ;
        if (++stg == STG) stg = 0;

        #pragma unroll
        for (int s = 0; s < 2; s++) {
            const int k8 = s * 8;
            float af[2][4];
            #pragma unroll
            for (int im = 0; im < 2; im++) {
                int mb = wm + im * 16;
                af[im][0] = As[(mb + g    ) * SA + k8 + tig    ];
                af[im][1] = As[(mb + g + 8) * SA + k8 + tig    ];
                af[im][2] = As[(mb + g    ) * SA + k8 + tig + 4];
                af[im][3] = As[(mb + g + 8) * SA + k8 + tig + 4];
            }
            #pragma unroll
            for (int in_ = 0; in_ < 4; in_++) {
                int nb = wn + in_ * 8;
                float bf[2];
                bf[0] = Bs[(k8 + tig    ) * SB + nb + g];
                bf[1] = Bs[(k8 + tig + 4) * SB + nb + g];
                #pragma unroll
                for (int im = 0; im < 2; im++)
                    mma_tf32(acc[im][in_], af[im], bf);
            }
        }
    }

    #pragma unroll
    for (int in_ = 0; in_ < 4; in_++) {
        int n = bn + wn + in_ * 8 + 2 * tig;
        float2 bv = *(const float2*)&bias[n];
        #pragma unroll
        for (int im = 0; im < 2; im++) {
            #pragma unroll
            for (int half = 0; half < 2; half++) {
                int m = bm + wm + im * 16 + g + half * 8;
                float2 r;
                r.x = acc[im][in_][half * 2 + 0] + bv.x;
                r.y = acc[im][in_][half * 2 + 1] + bv.y;
                if (EPI == 0) { r.x *= alpha; r.y *= alpha; }
                else if (EPI == 1) { r.x = fmaxf(r.x, 0.f); r.y = fmaxf(r.y, 0.f); }
                else {
                    float2 rr = *(const float2*)&resid[(size_t)m * Nc + n];
                    r.x += rr.x; r.y += rr.y;
                }
                *(float2*)&C[(size_t)m * Nc + n] = r;
            }
        }
    }
}

template<int EPI>
__global__ void __launch_bounds__(GTHR, 5)
gemm_pipe(const float* __restrict__ A, const float* __restrict__ W,
          const float* __restrict__ bias, const float* __restrict__ resid,
          float* __restrict__ C, int K, int Nc, float alpha,
          const int* __restrict__ num_nodes)
{
    const int bm = blockIdx.y * BM, bn = blockIdx.x * BN;
    if ((bm & (Nn - 1)) >= __ldg(&num_nodes[bm >> 9])) return;
    gemm_body<EPI>(A, W, bias, resid, C, K, Nc, alpha, bm, bn);
}

// ============ GEMM variant B: 64x128x16, 128 threads, 4 stages ==============
// warp tile 32x64 -> LDS:mma = 1.5 (vs 2.0). Used where grid is large (QKV, FFN1).
#define BN2 128
#define SB2 136
#define BSZ2 (BK * SB2)                     // 2176
#define STG_FLOATS2 (ASZ + BSZ2)            // 3456
#define GEMM_SMEM2 (STG * STG_FLOATS2 * 4)  // 55296 bytes

template<int EPI>
__device__ __forceinline__ void gemm_body_w(
    const float* __restrict__ A, const float* __restrict__ W,
    const float* __restrict__ bias,
    float* __restrict__ C, int K, int Nc, float alpha, int bm, int bn)
{
    extern __shared__ __align__(16) float sm[];

    const int tid  = threadIdx.x;
    const int wid  = tid >> 5, lane = tid & 31;
    const int g    = lane >> 2, tig = lane & 3;
    const int wm   = (wid & 1) * 32;
    const int wn   = (wid >> 1) * 64;
    const int KT   = K >> 4;

    const float* Ab = A + (size_t)bm * K;
    const float* Wb = W + bn;

    float acc[2][8][4];
    #pragma unroll
    for (int i = 0; i < 2; i++)
        #pragma unroll
        for (int j = 0; j < 8; j++)
            #pragma unroll
            for (int q = 0; q < 4; q++) acc[i][j][q] = 0.f;

    auto issue = [&](int stg, int kt) {
        float* As = sm + stg * STG_FLOATS2;
        float* Bs = As + ASZ;
        const int k0 = kt * BK;
        #pragma unroll
        for (int i = 0; i < 2; i++) {          // A: 256 float4
            int idx = tid + GTHR * i;
            int m = idx >> 2, kq = (idx & 3) * 4;
            cp_async16(As + m * SA + kq, Ab + (size_t)m * K + k0 + kq);
        }
        #pragma unroll
        for (int i = 0; i < 4; i++) {          // B: 16x128 = 512 float4
            int idx = tid + GTHR * i;
            int kr = idx >> 5, c4 = (idx & 31) * 4;
            cp_async16(Bs + kr * SB2 + c4, Wb + (size_t)(k0 + kr) * Nc + c4);
        }
    };

    #pragma unroll
    for (int s = 0; s < STG - 1; s++) { issue(s, s); cp_commit(); }

    int stg = 0, stg_next = STG - 1;
    for (int kt = 0; kt < KT; kt++) {
        cp_wait<STG - 2>();
        __syncthreads();

        int knext = kt + STG - 1;
        if (knext < KT) issue(stg_next, knext);
        cp_commit();
        if (++stg_next == STG) stg_next = 0;

        const float* As = sm + stg * STG_FLOATS2;
        const float* Bs = As + ASZ;
        if (++stg == STG) stg = 0;

        #pragma unroll
        for (int s = 0; s < 2; s++) {
            const int k8 = s * 8;
            float af[2][4];
            #pragma unroll
            for (int im = 0; im < 2; im++) {
                int mb = wm + im * 16;
                af[im][0] = As[(mb + g    ) * SA + k8 + tig    ];
                af[im][1] = As[(mb + g + 8) * SA + k8 + tig    ];
                af[im][2] = As[(mb + g    ) * SA + k8 + tig + 4];
                af[im][3] = As[(mb + g + 8) * SA + k8 + tig + 4];
            }
            #pragma unroll
            for (int in_ = 0; in_ < 8; in_++) {
                int nb = wn + in_ * 8;
                float bf[2];
                bf[0] = Bs[(k8 + tig    ) * SB2 + nb + g];
                bf[1] = Bs[(k8 + tig + 4) * SB2 + nb + g];
                #pragma unroll
                for (int im = 0; im < 2; im++)
                    mma_tf32(acc[im][in_], af[im], bf);
            }
        }
    }

    #pragma unroll
    for (int in_ = 0; in_ < 8; in_++) {
        int n = bn + wn + in_ * 8 + 2 * tig;
        float2 bv = *(const float2*)&bias[n];
        #pragma unroll
        for (int im = 0; im < 2; im++) {
            #pragma unroll
            for (int half = 0; half < 2; half++) {
                int m = bm + wm + im * 16 + g + half * 8;
                float2 r;
                r.x = acc[im][in_][half * 2 + 0] + bv.x;
                r.y = acc[im][in_][half * 2 + 1] + bv.y;
                if (EPI == 0) { r.x *= alpha; r.y *= alpha; }
                else if (EPI == 1) { r.x = fmaxf(r.x, 0.f); r.y = fmaxf(r.y, 0.f); }
                *(float2*)&C[(size_t)m * Nc + n] = r;
            }
        }
    }
}

// FFN1: relu epilogue, wide tile
__global__ void __launch_bounds__(GTHR, 4)
ffn1_wide(const float* __restrict__ A, const float* __restrict__ W,
          const float* __restrict__ bias, float* __restrict__ C,
          const int* __restrict__ num_nodes)
{
    const int bm = blockIdx.y * BM, bn = blockIdx.x * BN2;
    if ((bm & (Nn - 1)) >= __ldg(&num_nodes[bm >> 9])) return;
    gemm_body_w<1>(A, W, bias, C, Ff, HIDD, 1.f, bm, bn);
}

// QKV: wide tile, z selects projection
__global__ void __launch_bounds__(GTHR, 4)
qkv_wide(const float* __restrict__ A,
         const float* __restrict__ Wq, const float* __restrict__ Wk,
         const float* __restrict__ Wv,
         const float* __restrict__ bq, const float* __restrict__ bk,
         const float* __restrict__ bv,
         float* __restrict__ Cq, float* __restrict__ Ck, float* __restrict__ Cv,
         float qscale, const int* __restrict__ num_nodes)
{
    const int bm = blockIdx.y * BM, bn = blockIdx.x * BN2;
    if ((bm & (Nn - 1)) >= __ldg(&num_nodes[bm >> 9])) return;
    const int z = blockIdx.z;
    const float* W = (z == 0) ? Wq : (z == 1) ? Wk : Wv;
    const float* b = (z == 0) ? bq : (z == 1) ? bk : bv;
    float*       C = (z == 0) ? Cq : (z == 1) ? Ck : Cv;
    float alpha = (z == 0) ? qscale : 1.f;
    gemm_body_w<0>(A, W, b, C, Ff, Ff, alpha, bm, bn);
}

// ---------------- flash attention (R12: dist_idx + sSpH + dbuf) --------------
#define FS_K 36
#define FS_V 40
#define FS_P 68
#define KSZ (64 * FS_K)
#define VSZ (64 * FS_V)
#define FO_K 0
#define FO_V (FO_K + 2 * KSZ)
#define FO_P (FO_V + 2 * VSZ)
#define FO_SPH (FO_P + 128 * FS_P)
#define ATTN_SMEM_BYTES ((FO_SPH + 16) * 4)

__global__ void __launch_bounds__(256, 2)
attn_flash(const float* __restrict__ q, const float* __restrict__ k,
           const float* __restrict__ v,
           const int*   __restrict__ dist_idx,
           const float* __restrict__ spatial,
           const int*   __restrict__ num_nodes,
           float* __restrict__ o)
{
    extern __shared__ __align__(16) float sm[];
    float* sKb  = sm + FO_K;
    float* sVb  = sm + FO_V;
    float* sP   = sm + FO_P;
    float* sSpH = sm + FO_SPH;

    const int tid = threadIdx.x;
    const int it = blockIdx.x, h = blockIdx.y, b = blockIdx.z;
    const int i0 = it * 128;
    const int nn = num_nodes[b];
    if (i0 >= nn) return;

    const int jt_max = (nn + 63) >> 6;

    const int w = tid >> 5, lane = tid & 31;
    const int g = lane >> 2, tig = lane & 3;
    const int wm = w * 16;

    if (tid < 12) sSpH[tid] = spatial[tid * Hh + h];

    const float* kb0 = k + ((size_t)b * Nn) * Ff + h * DH;
    const float* vb0 = v + ((size_t)b * Nn) * Ff + h * DH;

    auto issue_kv = [&](int buf, int j0) {
        float* sK = sKb + buf * KSZ;
        float* sV = sVb + buf * VSZ;
        #pragma unroll
        for (int i = 0; i < 2; i++) {
            int idx = tid + 256 * i;
            int r = idx >> 3, d4 = (idx & 7) * 4;
            cp_async16(sK + r * FS_K + d4, kb0 + (size_t)(j0 + r) * Ff + d4);
            cp_async16(sV + r * FS_V + d4, vb0 + (size_t)(j0 + r) * Ff + d4);
        }
    };

    issue_kv(0, 0); cp_commit();

    const int rg  = wm + g;
    const int rg8 = wm + g + 8;

    const float* qb = q + ((size_t)(b * Nn + i0)) * Ff + h * DH;
    float qreg[4][4];
    #pragma unroll
    for (int kt = 0; kt < 4; kt++) {
        const int k8 = kt * 8;
        qreg[kt][0] = qb[(size_t)rg  * Ff + k8 + tig    ];
        qreg[kt][1] = qb[(size_t)rg8 * Ff + k8 + tig    ];
        qreg[kt][2] = qb[(size_t)rg  * Ff + k8 + tig + 4];
        qreg[kt][3] = qb[(size_t)rg8 * Ff + k8 + tig + 4];
    }

    const bool vi0 = (i0 + rg ) < nn;
    const bool vi1 = (i0 + rg8) < nn;
    const int* dr0 = dist_idx + ((size_t)(b * Nn + i0 + rg )) * Nn;
    const int* dr1 = dist_idx + ((size_t)(b * Nn + i0 + rg8)) * Nn;

    float m_run0 = -3.4e38f, m_run1 = -3.4e38f;
    float l_run0 = 0.f, l_run1 = 0.f;

    float oacc[4][4];
    #pragma unroll
    for (int i = 0; i < 4; i++)
        #pragma unroll
        for (int j = 0; j < 4; j++) oacc[i][j] = 0.f;

    for (int jt = 0; jt < jt_max; jt++) {
        const int j0 = jt * 64;
        const int buf = jt & 1;
        const float* sK = sKb + buf * KSZ;
        const float* sV = sVb + buf * VSZ;

        cp_wait<0>();
        __syncthreads();

        if (jt + 1 < jt_max) { issue_kv(buf ^ 1, j0 + 64); }
        cp_commit();

        float acc[8][4];
        #pragma unroll
        for (int i = 0; i < 8; i++)
            #pragma unroll
            for (int j = 0; j < 4; j++) acc[i][j] = 0.f;

        #pragma unroll
        for (int kt = 0; kt < 4; kt++) {
            const int k8 = kt * 8;
            #pragma unroll
            for (int nt = 0; nt < 8; nt++) {
                int nb = nt * 8;
                float bf[2];
                bf[0] = sK[(nb + g) * FS_K + k8 + tig    ];
                bf[1] = sK[(nb + g) * FS_K + k8 + tig + 4];
                mma_tf32(acc[nt], qreg[kt], bf);
            }
        }

        #pragma unroll
        for (int nt = 0; nt < 8; nt++) {
            int colb = j0 + nt * 8 + 2 * tig;
            int2 d0 = *(const int2*)(dr0 + colb);
            int2 d1 = *(const int2*)(dr1 + colb);
            bool m00 = (colb     >= nn) || ((!vi0) && (colb     >= 1));
            bool m01 = (colb + 1 >= nn) || ((!vi0) && (colb + 1 >= 1));
            bool m10 = (colb     >= nn) || ((!vi1) && (colb     >= 1));
            bool m11 = (colb + 1 >= nn) || ((!vi1) && (colb + 1 >= 1));
            acc[nt][0] = m00 ? -1e9f : acc[nt][0] + sSpH[d0.x];
            acc[nt][1] = m01 ? -1e9f : acc[nt][1] + sSpH[d0.y];
            acc[nt][2] = m10 ? -1e9f : acc[nt][2] + sSpH[d1.x];
            acc[nt][3] = m11 ? -1e9f : acc[nt][3] + sSpH[d1.y];
        }

        float tm0 = -3.4e38f, tm1 = -3.4e38f;
        #pragma unroll
        for (int nt = 0; nt < 8; nt++) {
            tm0 = fmaxf(tm0, fmaxf(acc[nt][0], acc[nt][1]));
            tm1 = fmaxf(tm1, fmaxf(acc[nt][2], acc[nt][3]));
        }
        #pragma unroll
        for (int off = 1; off <= 2; off <<= 1) {
            tm0 = fmaxf(tm0, __shfl_xor_sync(0xffffffffu, tm0, off));
            tm1 = fmaxf(tm1, __shfl_xor_sync(0xffffffffu, tm1, off));
        }

        const float nm0 = fmaxf(m_run0, tm0);
        const float nm1 = fmaxf(m_run1, tm1);
        const float f0 = __expf(m_run0 - nm0);
        const float f1 = __expf(m_run1 - nm1);
        m_run0 = nm0; m_run1 = nm1;

        float s0 = 0.f, s1 = 0.f;
        #pragma unroll
        for (int nt = 0; nt < 8; nt++) {
            int lcol = nt * 8 + 2 * tig;
            float p00 = __expf(acc[nt][0] - nm0);
            float p01 = __expf(acc[nt][1] - nm0);
            float p10 = __expf(acc[nt][2] - nm1);
            float p11 = __expf(acc[nt][3] - nm1);
            s0 += p00 + p01;
            s1 += p10 + p11;
            *(float2*)&sP[rg  * FS_P + lcol] = make_float2(p00, p01);
            *(float2*)&sP[rg8 * FS_P + lcol] = make_float2(p10, p11);
        }
        #pragma unroll
        for (int off = 1; off <= 2; off <<= 1) {
            s0 += __shfl_xor_sync(0xffffffffu, s0, off);
            s1 += __shfl_xor_sync(0xffffffffu, s1, off);
        }
        l_run0 = l_run0 * f0 + s0;
        l_run1 = l_run1 * f1 + s1;

        __syncwarp();

        #pragma unroll
        for (int nt = 0; nt < 4; nt++) {
            oacc[nt][0] *= f0; oacc[nt][1] *= f0;
            oacc[nt][2] *= f1; oacc[nt][3] *= f1;
        }

        #pragma unroll
        for (int kt = 0; kt < 8; kt++) {
            const int kc = kt * 8;
            float a[4];
            a[0] = sP[rg  * FS_P + kc + tig    ];
            a[1] = sP[rg8 * FS_P + kc + tig    ];
            a[2] = sP[rg  * FS_P + kc + tig + 4];
            a[3] = sP[rg8 * FS_P + kc + tig + 4];
            #pragma unroll
            for (int nt = 0; nt < 4; nt++) {
                int nb = nt * 8;
                float bf[2];
                bf[0] = sV[(kc + tig    ) * FS_V + nb + g];
                bf[1] = sV[(kc + tig + 4) * FS_V + nb + g];
                mma_tf32(oacc[nt], a, bf);
            }
        }
    }

    const float inv0 = 1.f / l_run0;
    const float inv1 = 1.f / l_run1;
    #pragma unroll
    for (int nt = 0; nt < 4; nt++) {
        int col = h * DH + nt * 8 + 2 * tig;
        *(float2*)&o[((size_t)(b * Nn + i0 + rg )) * Ff + col] =
            make_float2(oacc[nt][0] * inv0, oacc[nt][1] * inv0);
        *(float2*)&o[((size_t)(b * Nn + i0 + rg8)) * Ff + col] =
            make_float2(oacc[nt][2] * inv1, oacc[nt][3] * inv1);
    }
}

// ---------------- LayerNorm: one warp per row, shuffle-only ----------------
__global__ void __launch_bounds__(256)
ln_kernel(float* __restrict__ x,
          const float* __restrict__ gamma,
          const float* __restrict__ beta,
          const int* __restrict__ num_nodes)
{
    const int warp = threadIdx.x >> 5, lane = threadIdx.x & 31;
    const int row = blockIdx.x * 8 + warp;
    if ((row & (Nn - 1)) >= __ldg(&num_nodes[row >> 9])) return;

    float* xr = x + (size_t)row * Ff;
    float4 v[4];
    #pragma unroll
    for (int i = 0; i < 4; i++)
        v[i] = *(const float4*)(xr + lane * 4 + i * 128);

    float s = 0.f;
    #pragma unroll
    for (int i = 0; i < 4; i++) s += v[i].x + v[i].y + v[i].z + v[i].w;
    s = warp_sum(s);
    const float mean = s * (1.f / 512.f);

    float s2 = 0.f;
    #pragma unroll
    for (int i = 0; i < 4; i++) {
        float dx = v[i].x - mean, dy = v[i].y - mean;
        float dz = v[i].z - mean, dw = v[i].w - mean;
        s2 += dx * dx + dy * dy + dz * dz + dw * dw;
    }
    s2 = warp_sum(s2);
    const float inv = rsqrtf(s2 * (1.f / 512.f) + 1e-5f);

    #pragma unroll
    for (int i = 0; i < 4; i++) {
        float4 gm = *(const float4*)(gamma + lane * 4 + i * 128);
        float4 bt = *(const float4*)(beta  + lane * 4 + i * 128);
        float4 r;
        r.x = (v[i].x - mean) * inv * gm.x + bt.x;
        r.y = (v[i].y - mean) * inv * gm.y + bt.y;
        r.z = (v[i].z - mean) * inv * gm.z + bt.z;
        r.w = (v[i].w - mean) * inv * gm.w + bt.w;
        *(float4*)(xr + lane * 4 + i * 128) = r;
    }
}

// ---------------- pooled classifier ----------------
__global__ void pool_kernel(const float* __restrict__ x,
                            const int*   __restrict__ num_nodes,
                            const float* __restrict__ clf_w,
                            const float* __restrict__ clf_b,
                            float* __restrict__ out)
{
    __shared__ float red[8];
    const int b = blockIdx.x, tid = threadIdx.x;
    const int lane = tid & 31, warp = tid >> 5;
    const int nn = num_nodes[b];
    const float* xb = x + (size_t)b * Nn * Ff;
    float local = 0.f;
    const int total = nn * Ff;
    for (int i = tid; i < total; i += 256)
        local += xb[i] * clf_w[i & (Ff - 1)];
    local = warp_sum(local);
    if (lane == 0) red[warp] = local;
    __syncthreads();
    if (tid == 0) {
        float tot = 0.f;
        #pragma unroll
        for (int i = 0; i < 8; i++) tot += red[i];
        float z = tot / (float)nn + clf_b[0];
        out[b] = 1.f / (1.f + expf(-z));
    }
}

// ---------------- host launcher ----------------
extern "C" void kernel_launch(void* const* d_in, const int* in_sizes, int n_in,
                              void* d_out, int out_size)
{
    const float* nfeats   = (const float*)d_in[0];
    const int*   degrees  = (const int*)  d_in[1];
    const int*   dist_idx = (const int*)  d_in[2];
    const int*   num_nodes= (const int*)  d_in[3];
    const float* deg_in   = (const float*)d_in[4];
    const float* deg_out  = (const float*)d_in[5];
    const float* spatial  = (const float*)d_in[6];
    const float* Wq = (const float*)d_in[7];
    const float* bq = (const float*)d_in[8];
    const float* Wk = (const float*)d_in[9];
    const float* bk = (const float*)d_in[10];
    const float* Wv = (const float*)d_in[11];
    const float* bv = (const float*)d_in[12];
    const float* Wo = (const float*)d_in[13];
    const float* bo = (const float*)d_in[14];
    const float* ln1_s = (const float*)d_in[15];
    const float* ln1_b = (const float*)d_in[16];
    const float* W1 = (const float*)d_in[17];
    const float* b1 = (const float*)d_in[18];
    const float* W2 = (const float*)d_in[19];
    const float* b2 = (const float*)d_in[20];
    const float* ln2_s = (const float*)d_in[21];
    const float* ln2_b = (const float*)d_in[22];
    const float* clf_w = (const float*)d_in[23];
    const float* clf_b = (const float*)d_in[24];
    float* out = (float*)d_out;

    float *px, *pq, *pk, *pv, *pao, *ph;
    cudaGetSymbolAddress((void**)&px,  g_x);
    cudaGetSymbolAddress((void**)&pq,  g_q);
    cudaGetSymbolAddress((void**)&pk,  g_k);
    cudaGetSymbolAddress((void**)&pv,  g_v);
    cudaGetSymbolAddress((void**)&pao, g_ao);
    cudaGetSymbolAddress((void**)&ph,  g_h);

    cudaFuncSetAttribute(attn_flash,
                         cudaFuncAttributeMaxDynamicSharedMemorySize,
                         ATTN_SMEM_BYTES);
    cudaFuncSetAttribute(qkv_wide,
                         cudaFuncAttributeMaxDynamicSharedMemorySize, GEMM_SMEM2);
    cudaFuncSetAttribute(ffn1_wide,
                         cudaFuncAttributeMaxDynamicSharedMemorySize, GEMM_SMEM2);
    cudaFuncSetAttribute(gemm_pipe<0>,
                         cudaFuncAttributeMaxDynamicSharedMemorySize, GEMM_SMEM);
    cudaFuncSetAttribute(gemm_pipe<1>,
                         cudaFuncAttributeMaxDynamicSharedMemorySize, GEMM_SMEM);
    cudaFuncSetAttribute(gemm_pipe<2>,
                         cudaFuncAttributeMaxDynamicSharedMemorySize, GEMM_SMEM);

    build_x_kernel<<<(Bb * Nn * Ff) / 256, 256>>>(nfeats, degrees, num_nodes,
                                                  deg_in, deg_out, px);

    const float scale = 0.17677669529663687f;  // 1/sqrt(32)
    const dim3 g512(Ff / BN, MM / BM);          // (8, 128)  narrow variant
    const dim3 gQKVw(Ff / BN2, MM / BM, 3);     // (4, 128, 3) wide variant
    const dim3 gHidw(HIDD / BN2, MM / BM);      // (16, 128)  wide variant

    for (int l = 0; l < LLa; l++) {
        qkv_wide<<<gQKVw, GTHR, GEMM_SMEM2>>>(
            px,
            Wq + (size_t)l * Ff * Ff, Wk + (size_t)l * Ff * Ff, Wv + (size_t)l * Ff * Ff,
            bq + l * Ff, bk + l * Ff, bv + l * Ff,
            pq, pk, pv, scale, num_nodes);

        attn_flash<<<dim3(Nn / 128, Hh, Bb), 256, ATTN_SMEM_BYTES>>>(
            pq, pk, pv, dist_idx, spatial, num_nodes, pao);

        gemm_pipe<2><<<g512, GTHR, GEMM_SMEM>>>(pao, Wo + (size_t)l * Ff * Ff,
                                                bo + l * Ff, px, px, Ff, Ff, 1.f,
                                                num_nodes);
        ln_kernel<<<MM / 8, 256>>>(px, ln1_s + l * Ff, ln1_b + l * Ff, num_nodes);

        ffn1_wide<<<gHidw, GTHR, GEMM_SMEM2>>>(px, W1 + (size_t)l * Ff * HIDD,
                                               b1 + l * HIDD, ph, num_nodes);
        gemm_pipe<2><<<g512, GTHR, GEMM_SMEM>>>(ph, W2 + (size_t)l * HIDD * Ff,
                                                b2 + l * Ff, px, px, HIDD, Ff, 1.f,
                                                num_nodes);
        ln_kernel<<<MM / 8, 256>>>(px, ln2_s + l * Ff, ln2_b + l * Ff, num_nodes);
    }

    pool_kernel<<<Bb, 256>>>(px, num_nodes, clf_w, clf_b, out);
}